// round 4
// baseline (speedup 1.0000x reference)
#include <cuda_runtime.h>
#include <cuda_bf16.h>

// ---------------------------------------------------------------------------
// Problem constants
// ---------------------------------------------------------------------------
namespace {
constexpr int NB    = 4096;          // batch
constexpr int NN    = 30;            // nodes
constexpr int INC   = 512;           // input channels
constexpr int NF    = 128;           // hidden features
constexpr int NC    = 9;             // output channels
constexpr int MROWS = NB * NN;       // 122880 (divisible by 128)
}

// ---------------------------------------------------------------------------
// Scratch (device globals: allocation is forbidden)
// ---------------------------------------------------------------------------
__device__ float g_XW[(size_t)NB * NN * NF];   // real @ W1
__device__ float g_H1[(size_t)NB * NN * NF];   // relu(An @ XW + b1)
__device__ float g_G [(size_t)NB * NN * NF];   // H1 @ W2
__device__ float g_An[(size_t)NB * NN * NN];   // normalized adjacency

// ---------------------------------------------------------------------------
// Helpers
// ---------------------------------------------------------------------------
__device__ __forceinline__ void mma16816(float* c, const unsigned* a, const unsigned* b) {
    asm volatile(
        "mma.sync.aligned.m16n8k16.row.col.f32.bf16.bf16.f32 "
        "{%0,%1,%2,%3}, {%4,%5,%6,%7}, {%8,%9}, {%0,%1,%2,%3};\n"
        : "+f"(c[0]), "+f"(c[1]), "+f"(c[2]), "+f"(c[3])
        : "r"(a[0]), "r"(a[1]), "r"(a[2]), "r"(a[3]),
          "r"(b[0]), "r"(b[1]));
}

// Split 4 consecutive fp32 into bf16 hi + bf16 residual lo, store to smem.
__device__ __forceinline__ void store_split4(__nv_bfloat16* hi, __nv_bfloat16* lo, float4 v) {
    __nv_bfloat16 hx = __float2bfloat16_rn(v.x);
    __nv_bfloat16 hy = __float2bfloat16_rn(v.y);
    __nv_bfloat16 hz = __float2bfloat16_rn(v.z);
    __nv_bfloat16 hw = __float2bfloat16_rn(v.w);
    *(__nv_bfloat162*)(hi)     = __halves2bfloat162(hx, hy);
    *(__nv_bfloat162*)(hi + 2) = __halves2bfloat162(hz, hw);
    *(__nv_bfloat162*)(lo)     = __floats2bfloat162_rn(v.x - __bfloat162float(hx),
                                                       v.y - __bfloat162float(hy));
    *(__nv_bfloat162*)(lo + 2) = __floats2bfloat162_rn(v.z - __bfloat162float(hz),
                                                       v.w - __bfloat162float(hw));
}

// Pack two bf16 (from two different smem rows) into one mma register.
__device__ __forceinline__ unsigned pack2(const __nv_bfloat16* p0, const __nv_bfloat16* p1) {
    unsigned u0 = *(const unsigned short*)p0;
    unsigned u1 = *(const unsigned short*)p1;
    return u0 | (u1 << 16);
}

// ---------------------------------------------------------------------------
// Split-bf16 GEMM:  C[M,128] = A[M,K] @ B[K,128]   (fp32 in, fp32 out,
// 3-pass hi/lo bf16 mma -> ~fp32 accuracy). Block tile 128x128xBK16,
// 8 warps in 2x4, warp tile 64x32.
// SRC: 0 -> A = param (real), 1 -> A = g_H1.  DST: 0 -> g_XW, 1 -> g_G.
// ---------------------------------------------------------------------------
template <int K, int SRC, int DST>
__global__ void __launch_bounds__(256) gemm_split(const float* __restrict__ Ain,
                                                  const float* __restrict__ Bw) {
    const float* __restrict__ A = (SRC == 0) ? Ain : (const float*)g_H1;
    float* __restrict__ C = (DST == 0) ? g_XW : g_G;

    // padded strides: A row = 24 bf16 (conflict-free frag loads), B row = 136 bf16
    __shared__ __align__(16) __nv_bfloat16 sAhi[128][24];
    __shared__ __align__(16) __nv_bfloat16 sAlo[128][24];
    __shared__ __align__(16) __nv_bfloat16 sBhi[16][136];
    __shared__ __align__(16) __nv_bfloat16 sBlo[16][136];

    const int tid  = threadIdx.x;
    const int warp = tid >> 5, lane = tid & 31;
    const int wm = warp >> 2, wn = warp & 3;    // 2 x 4 warp grid
    const int g  = lane >> 2, tq = lane & 3;
    const long mbase = (long)blockIdx.x * 128;

    float acc[4][4][4];
#pragma unroll
    for (int a = 0; a < 4; a++)
#pragma unroll
        for (int b = 0; b < 4; b++)
#pragma unroll
            for (int c = 0; c < 4; c++) acc[a][b][c] = 0.f;

    // global->register staging assignment
    const int rA0 = tid >> 2;            // 0..63 (and +64)
    const int kA0 = (tid & 3) * 4;       // 0,4,8,12
    const int rB0 = tid >> 5;            // 0..7 (and +8)
    const int nB0 = (tid & 31) * 4;      // 0..124

    const float* Aptr0 = A + (mbase + rA0) * K + kA0;
    const float* Aptr1 = Aptr0 + (long)64 * K;
    const float* Bptr0 = Bw + rB0 * 128 + nB0;
    const float* Bptr1 = Bptr0 + 8 * 128;

    float4 a0 = *(const float4*)Aptr0;
    float4 a1 = *(const float4*)Aptr1;
    float4 b0 = *(const float4*)Bptr0;
    float4 b1 = *(const float4*)Bptr1;

    const int iters = K / 16;
    for (int it = 0; it < iters; ++it) {
        // stage registers -> smem (with fp32 -> bf16 hi/lo split)
        store_split4(&sAhi[rA0][kA0],      &sAlo[rA0][kA0],      a0);
        store_split4(&sAhi[rA0 + 64][kA0], &sAlo[rA0 + 64][kA0], a1);
        store_split4(&sBhi[rB0][nB0],      &sBlo[rB0][nB0],      b0);
        store_split4(&sBhi[rB0 + 8][nB0],  &sBlo[rB0 + 8][nB0],  b1);
        __syncthreads();

        if (it + 1 < iters) {   // prefetch next K-slab while computing
            a0 = *(const float4*)(Aptr0 + (it + 1) * 16);
            a1 = *(const float4*)(Aptr1 + (it + 1) * 16);
            b0 = *(const float4*)(Bptr0 + (long)(it + 1) * 16 * 128);
            b1 = *(const float4*)(Bptr1 + (long)(it + 1) * 16 * 128);
        }

        // B fragments (col-major 16x8): {B[2tq,n],B[2tq+1,n]}, {B[2tq+8,n],B[2tq+9,n]}
        unsigned bh[4][2], bl[4][2];
#pragma unroll
        for (int nt = 0; nt < 4; nt++) {
            const int n = wn * 32 + nt * 8 + g;
            bh[nt][0] = pack2(&sBhi[2 * tq][n],     &sBhi[2 * tq + 1][n]);
            bh[nt][1] = pack2(&sBhi[2 * tq + 8][n], &sBhi[2 * tq + 9][n]);
            bl[nt][0] = pack2(&sBlo[2 * tq][n],     &sBlo[2 * tq + 1][n]);
            bl[nt][1] = pack2(&sBlo[2 * tq + 8][n], &sBlo[2 * tq + 9][n]);
        }

#pragma unroll
        for (int mt = 0; mt < 4; mt++) {
            const int r = wm * 64 + mt * 16 + g;
            unsigned ah[4], al[4];
            ah[0] = *(const unsigned*)&sAhi[r][2 * tq];
            ah[1] = *(const unsigned*)&sAhi[r + 8][2 * tq];
            ah[2] = *(const unsigned*)&sAhi[r][2 * tq + 8];
            ah[3] = *(const unsigned*)&sAhi[r + 8][2 * tq + 8];
            al[0] = *(const unsigned*)&sAlo[r][2 * tq];
            al[1] = *(const unsigned*)&sAlo[r + 8][2 * tq];
            al[2] = *(const unsigned*)&sAlo[r][2 * tq + 8];
            al[3] = *(const unsigned*)&sAlo[r + 8][2 * tq + 8];
#pragma unroll
            for (int nt = 0; nt < 4; nt++) {
                mma16816(acc[mt][nt], ah, bh[nt]);   // hi*hi
                mma16816(acc[mt][nt], ah, bl[nt]);   // hi*lo
                mma16816(acc[mt][nt], al, bh[nt]);   // lo*hi
            }
        }
        __syncthreads();
    }

    // epilogue: fp32 store
#pragma unroll
    for (int mt = 0; mt < 4; mt++) {
        const long row = mbase + wm * 64 + mt * 16 + g;
#pragma unroll
        for (int nt = 0; nt < 4; nt++) {
            const int col = wn * 32 + nt * 8 + 2 * tq;
            float2 v0 = make_float2(acc[mt][nt][0], acc[mt][nt][1]);
            float2 v1 = make_float2(acc[mt][nt][2], acc[mt][nt][3]);
            *(float2*)&C[row * 128 + col]       = v0;
            *(float2*)&C[(row + 8) * 128 + col] = v1;
        }
    }
}

// ---------------------------------------------------------------------------
// Kernel 2: per batch -- build normalized adjacency, H1 = relu(An @ XW + b1)
// One block per batch, 256 threads.
// ---------------------------------------------------------------------------
__global__ void __launch_bounds__(256) prop1_kernel(const float* __restrict__ graph,
                                                    const float* __restrict__ b1) {
    const int b = blockIdx.x, tid = threadIdx.x;
    __shared__ float sA[NN][32];
    __shared__ float sX[NN][NF];
    __shared__ float sdinv[NN];

    // A_hat: pattern of mean over bands, self-loops forced to 1
    const float* gb = graph + (size_t)b * 5 * NN * NN;
    for (int idx = tid; idx < NN * NN; idx += 256) {
        float s = gb[idx] + gb[idx + 900] + gb[idx + 1800] + gb[idx + 2700] + gb[idx + 3600];
        const int i = idx / NN, j = idx - i * NN;
        float a = (s != 0.0f) ? 1.0f : 0.0f;
        if (i == j) a = 1.0f;
        sA[i][j] = a;
    }
    // stage XW tile
    {
        const float4* xg = (const float4*)(g_XW + (size_t)b * NN * NF);
        float4* xs = (float4*)&sX[0][0];
        for (int idx = tid; idx < NN * NF / 4; idx += 256) xs[idx] = xg[idx];
    }
    __syncthreads();

    if (tid < NN) {
        float d = 0.f;
#pragma unroll
        for (int j = 0; j < NN; j++) d += sA[tid][j];
        sdinv[tid] = rsqrtf(d);   // deg >= 1 always (self-loop)
    }
    __syncthreads();

    for (int idx = tid; idx < NN * NN; idx += 256) {
        const int i = idx / NN, j = idx - i * NN;
        const float v = sdinv[i] * sA[i][j] * sdinv[j];
        sA[i][j] = v;
        g_An[(size_t)b * NN * NN + idx] = v;
    }
    __syncthreads();

    // H1[i][f] = relu(b1[f] + sum_j An[i][j] * XW[j][f])
    const int f = tid & 127;
    const int ih = tid >> 7;          // 0/1 -> rows [0,15) / [15,30)
    const float bb = b1[f];
    float acc[15];
#pragma unroll
    for (int t = 0; t < 15; t++) acc[t] = 0.f;
#pragma unroll
    for (int j = 0; j < NN; j++) {
        const float xv = sX[j][f];
#pragma unroll
        for (int t = 0; t < 15; t++) acc[t] += sA[ih * 15 + t][j] * xv;   // An broadcast
    }
    float* outp = g_H1 + (size_t)b * NN * NF + f;
#pragma unroll
    for (int t = 0; t < 15; t++)
        outp[(ih * 15 + t) * NF] = fmaxf(acc[t] + bb, 0.f);
}

// ---------------------------------------------------------------------------
// Kernel 4: per batch -- H2 = relu(An @ G + b2); x = relu(H2 @ Wlin + blin);
//           out = x @ Wconv^T + bconv
// ---------------------------------------------------------------------------
__global__ void __launch_bounds__(256) prop2_kernel(const float* __restrict__ b2,
                                                    const float* __restrict__ Wlin,
                                                    const float* __restrict__ blin,
                                                    const float* __restrict__ Wconv,
                                                    const float* __restrict__ bconv,
                                                    float* __restrict__ out) {
    const int b = blockIdx.x, tid = threadIdx.x;
    __shared__ float sA[NN][32];
    __shared__ float sG[NN][NF];
    __shared__ float sH[NN][NF];
    __shared__ float sx[NN];

    for (int idx = tid; idx < NN * NN; idx += 256) {
        const int i = idx / NN, j = idx - i * NN;
        sA[i][j] = g_An[(size_t)b * NN * NN + idx];
    }
    {
        const float4* gg = (const float4*)(g_G + (size_t)b * NN * NF);
        float4* gs = (float4*)&sG[0][0];
        for (int idx = tid; idx < NN * NF / 4; idx += 256) gs[idx] = gg[idx];
    }
    __syncthreads();

    const int f = tid & 127;
    const int ih = tid >> 7;
    const float bb = b2[f];
    float acc[15];
#pragma unroll
    for (int t = 0; t < 15; t++) acc[t] = 0.f;
#pragma unroll
    for (int j = 0; j < NN; j++) {
        const float xv = sG[j][f];
#pragma unroll
        for (int t = 0; t < 15; t++) acc[t] += sA[ih * 15 + t][j] * xv;
    }
#pragma unroll
    for (int t = 0; t < 15; t++)
        sH[ih * 15 + t][f] = fmaxf(acc[t] + bb, 0.f);
    __syncthreads();

    // x[r] = relu(dot(H2[r], Wlin) + blin)
    const int w = tid >> 5, lane = tid & 31;
    const float wl0 = Wlin[lane], wl1 = Wlin[lane + 32],
                wl2 = Wlin[lane + 64], wl3 = Wlin[lane + 96];
    for (int r = w; r < NN; r += 8) {
        float p = sH[r][lane] * wl0 + sH[r][lane + 32] * wl1 +
                  sH[r][lane + 64] * wl2 + sH[r][lane + 96] * wl3;
#pragma unroll
        for (int o = 16; o > 0; o >>= 1) p += __shfl_xor_sync(0xffffffffu, p, o);
        if (lane == 0) sx[r] = fmaxf(p + blin[0], 0.f);
    }
    __syncthreads();

    if (tid < NC) {
        float a = bconv[tid];
#pragma unroll
        for (int i = 0; i < NN; i++) a += sx[i] * Wconv[tid * NN + i];
        out[(size_t)b * NC + tid] = a;
    }
}

// ---------------------------------------------------------------------------
// Launch
// ---------------------------------------------------------------------------
extern "C" void kernel_launch(void* const* d_in, const int* in_sizes, int n_in,
                              void* d_out, int out_size) {
    const float* real  = (const float*)d_in[0];
    // d_in[1] = imag (unused by the reference)
    const float* graph = (const float*)d_in[2];
    const float* W1    = (const float*)d_in[3];
    const float* b1    = (const float*)d_in[4];
    const float* W2    = (const float*)d_in[5];
    const float* b2    = (const float*)d_in[6];
    const float* Wlin  = (const float*)d_in[7];
    const float* blin  = (const float*)d_in[8];
    const float* Wconv = (const float*)d_in[9];
    const float* bconv = (const float*)d_in[10];
    float* out = (float*)d_out;

    gemm_split<INC, 0, 0><<<MROWS / 128, 256>>>(real, W1);       // XW = real @ W1
    prop1_kernel<<<NB, 256>>>(graph, b1);                        // An, H1
    gemm_split<NF, 1, 1><<<MROWS / 128, 256>>>(nullptr, W2);     // G = H1 @ W2
    prop2_kernel<<<NB, 256>>>(b2, Wlin, blin, Wconv, bconv, out);
}